// round 3
// baseline (speedup 1.0000x reference)
#include <cuda_runtime.h>
#include <math.h>

#define Bz   64
#define Tt   128
#define TM1  127
#define Vv   10000
#define Ee   300
#define Hh   1024
#define G4   4096
#define MROWS (TM1*Bz)   // 8128

typedef unsigned long long ull;

// ---------------- scratch (device globals; no allocs allowed) ----------------
__device__ float g_xw[(size_t)MROWS * G4];     // precomputed x@w_ih0 + b0, layout (t,b,4H)
__device__ float g_h1all[(size_t)MROWS * Hh];  // all h1 states, layout (t,b,H)
__device__ float g_h0[2][Bz * Hh];             // ping-pong layer0 h state
__device__ float g_h1[2][Bz * Hh];             // ping-pong layer1 h state
__device__ float g_c0[Bz * Hh];
__device__ float g_c1[Bz * Hh];
__device__ float g_rowloss[MROWS];

// ---------------- f32x2 packed-FMA helpers (sm_100+) ----------------
__device__ __forceinline__ ull pk2(float x, float y) {
    ull r; asm("mov.b64 %0, {%1,%2};" : "=l"(r) : "f"(x), "f"(y)); return r;
}
__device__ __forceinline__ ull fma2(ull a, ull b, ull c) {
    ull d; asm("fma.rn.f32x2 %0, %1, %2, %3;" : "=l"(d) : "l"(a), "l"(b), "l"(c)); return d;
}
__device__ __forceinline__ float2 upk(ull v) {
    float2 f; asm("mov.b64 {%0,%1}, %2;" : "=f"(f.x), "=f"(f.y) : "l"(v)); return f;
}
__device__ __forceinline__ float sigf(float x) { return 1.0f / (1.0f + expf(-x)); }

// ---------------- init states ----------------
__global__ void k_init() {
    int i = blockIdx.x * blockDim.x + threadIdx.x;
    if (i < Bz * Hh) {
        g_h0[0][i] = 0.f; g_h1[0][i] = 0.f;
        g_c0[i] = 0.f;    g_c1[i] = 0.f;
    }
}

// ---------------- K2: xW = gather(emb) @ w_ih0 + b0 ----------------
// M=8128 (m = t*64+b), N=4096, K=300. 128x128 tile, 256 thr, 8x8/thread (f32x2 pairs).
__global__ __launch_bounds__(256) void k_xw(const int* __restrict__ sent,
                                            const float* __restrict__ wordvec,
                                            const float* __restrict__ wih0,
                                            const float* __restrict__ b0) {
    __shared__ float As[8][128];
    __shared__ float Bs[8][128];
    __shared__ int stok[128];

    int tid = threadIdx.x;
    int n0 = blockIdx.x * 128;
    int m0 = blockIdx.y * 128;

    if (tid < 128) {
        int m = m0 + tid;
        int mc = (m < MROWS) ? m : (MROWS - 1);
        int t = mc >> 6, b = mc & 63;
        stok[tid] = sent[b * Tt + t];
    }
    __syncthreads();

    int tx = tid & 15, ty = tid >> 4;
    ull acc[8][4];
#pragma unroll
    for (int i = 0; i < 8; i++)
#pragma unroll
        for (int j = 0; j < 4; j++) acc[i][j] = 0ULL;

    for (int k0 = 0; k0 < Ee; k0 += 8) {
#pragma unroll
        for (int p = 0; p < 4; p++) {
            int idx = tid + p * 256;
            int r = idx & 127, kk = idx >> 7;
            int k = k0 + kk;
            As[kk][r] = (k < Ee) ? wordvec[(size_t)stok[r] * Ee + k] : 0.f;
            Bs[kk][r] = (k < Ee) ? wih0[(size_t)k * G4 + n0 + r] : 0.f;
        }
        __syncthreads();
#pragma unroll
        for (int kk = 0; kk < 8; kk++) {
            ull bf[4];
#pragma unroll
            for (int j = 0; j < 4; j++) bf[j] = *(const ull*)&Bs[kk][32 * j + 2 * tx];
#pragma unroll
            for (int i = 0; i < 8; i++) {
                float a = As[kk][ty + 16 * i];
                ull a2 = pk2(a, a);
#pragma unroll
                for (int j = 0; j < 4; j++) acc[i][j] = fma2(a2, bf[j], acc[i][j]);
            }
        }
        __syncthreads();
    }

#pragma unroll
    for (int i = 0; i < 8; i++) {
        int m = m0 + ty + 16 * i;
        if (m >= MROWS) continue;
        float* orow = g_xw + (size_t)m * G4 + n0;
#pragma unroll
        for (int j = 0; j < 4; j++) {
            float2 v = upk(acc[i][j]);
            int c = 32 * j + 2 * tx;
            orow[c]     = v.x + b0[n0 + c];
            orow[c + 1] = v.y + b0[n0 + c + 1];
        }
    }
}

// ---------------- K3a: layer0 step: gates = xw[t] + h0 @ w_hh0; cell update -----
// 128 blocks: block nb owns 8 hidden units j0=nb*8; tile 64(b) x 32(c=g*8+jj).
__global__ __launch_bounds__(128) void k_l0(int t, int pp, const float* __restrict__ whh0) {
    __shared__ float sh_h[16][66];
    __shared__ float sh_w[16][32];
    __shared__ float sg[64][33];

    int tid = threadIdx.x;
    int j0 = blockIdx.x * 8;
    const float* hin = g_h0[pp];
    const float* xw = g_xw + (size_t)t * Bz * G4;
    int txc = tid & 7, tyr = tid >> 3;

    ull acc[4][2];
#pragma unroll
    for (int i = 0; i < 4; i++) { acc[i][0] = 0ULL; acc[i][1] = 0ULL; }

    for (int k0 = 0; k0 < Hh; k0 += 16) {
#pragma unroll
        for (int q = 0; q < 8; q++) {
            int idx = tid + q * 128;
            int kk = idx & 15, bb = idx >> 4;
            sh_h[kk][bb] = hin[bb * Hh + k0 + kk];
        }
#pragma unroll
        for (int q = 0; q < 4; q++) {
            int idx = tid + q * 128;
            int c = idx & 31, kk = idx >> 5;
            int col = ((c >> 3) << 10) + j0 + (c & 7);
            sh_w[kk][c] = whh0[(size_t)(k0 + kk) * G4 + col];
        }
        __syncthreads();
#pragma unroll
        for (int kk = 0; kk < 16; kk++) {
            ull b0p = *(const ull*)&sh_w[kk][2 * txc];
            ull b1p = *(const ull*)&sh_w[kk][2 * txc + 16];
#pragma unroll
            for (int i = 0; i < 4; i++) {
                float a = sh_h[kk][tyr + 16 * i];
                ull a2 = pk2(a, a);
                acc[i][0] = fma2(a2, b0p, acc[i][0]);
                acc[i][1] = fma2(a2, b1p, acc[i][1]);
            }
        }
        __syncthreads();
    }

#pragma unroll
    for (int i = 0; i < 4; i++) {
        int r = tyr + 16 * i;
#pragma unroll
        for (int jp = 0; jp < 2; jp++) {
            float2 v = upk(acc[i][jp]);
            int c = 2 * txc + 16 * jp;
            int col = ((c >> 3) << 10) + j0 + (c & 7);
            sg[r][c]     = v.x + xw[r * G4 + col];
            sg[r][c + 1] = v.y + xw[r * G4 + col + 1];
        }
    }
    __syncthreads();

#pragma unroll
    for (int p = 0; p < 4; p++) {
        int idx = tid + p * 128;
        int bb = idx & 63, jj = idx >> 6;
        float iv = sg[bb][jj],      fv = sg[bb][8 + jj];
        float gv = sg[bb][16 + jj], ov = sg[bb][24 + jj];
        int hi = bb * Hh + j0 + jj;
        float co = g_c0[hi];
        float cn = sigf(fv) * co + sigf(iv) * tanhf(gv);
        float hn = sigf(ov) * tanhf(cn);
        g_c0[hi] = cn;
        g_h0[pp ^ 1][hi] = hn;
    }
}

// ---------------- K3b: layer1 step: gates = h0new@w_ih1 + h1@w_hh1 + b1 --------
__global__ __launch_bounds__(128) void k_l1(int t, int pp,
                                            const float* __restrict__ wih1,
                                            const float* __restrict__ whh1,
                                            const float* __restrict__ b1) {
    __shared__ float sh_h[16][66];
    __shared__ float sh_w[16][32];
    __shared__ float sg[64][33];

    int tid = threadIdx.x;
    int j0 = blockIdx.x * 8;
    const float* h0n = g_h0[pp ^ 1];
    const float* h1o = g_h1[pp];
    int txc = tid & 7, tyr = tid >> 3;

    ull acc[4][2];
#pragma unroll
    for (int i = 0; i < 4; i++) { acc[i][0] = 0ULL; acc[i][1] = 0ULL; }

    for (int k0 = 0; k0 < 2 * Hh; k0 += 16) {
        const float* hsrc; const float* wsrc; int kb;
        if (k0 < Hh) { hsrc = h0n; wsrc = wih1; kb = k0; }
        else         { hsrc = h1o; wsrc = whh1; kb = k0 - Hh; }
#pragma unroll
        for (int q = 0; q < 8; q++) {
            int idx = tid + q * 128;
            int kk = idx & 15, bb = idx >> 4;
            sh_h[kk][bb] = hsrc[bb * Hh + kb + kk];
        }
#pragma unroll
        for (int q = 0; q < 4; q++) {
            int idx = tid + q * 128;
            int c = idx & 31, kk = idx >> 5;
            int col = ((c >> 3) << 10) + j0 + (c & 7);
            sh_w[kk][c] = wsrc[(size_t)(kb + kk) * G4 + col];
        }
        __syncthreads();
#pragma unroll
        for (int kk = 0; kk < 16; kk++) {
            ull b0p = *(const ull*)&sh_w[kk][2 * txc];
            ull b1p = *(const ull*)&sh_w[kk][2 * txc + 16];
#pragma unroll
            for (int i = 0; i < 4; i++) {
                float a = sh_h[kk][tyr + 16 * i];
                ull a2 = pk2(a, a);
                acc[i][0] = fma2(a2, b0p, acc[i][0]);
                acc[i][1] = fma2(a2, b1p, acc[i][1]);
            }
        }
        __syncthreads();
    }

#pragma unroll
    for (int i = 0; i < 4; i++) {
        int r = tyr + 16 * i;
#pragma unroll
        for (int jp = 0; jp < 2; jp++) {
            float2 v = upk(acc[i][jp]);
            int c = 2 * txc + 16 * jp;
            sg[r][c]     = v.x;
            sg[r][c + 1] = v.y;
        }
    }
    __syncthreads();

#pragma unroll
    for (int p = 0; p < 4; p++) {
        int idx = tid + p * 128;
        int bb = idx & 63, jj = idx >> 6;
        int j = j0 + jj;
        float iv = sg[bb][jj]      + b1[j];
        float fv = sg[bb][8 + jj]  + b1[Hh + j];
        float gv = sg[bb][16 + jj] + b1[2 * Hh + j];
        float ov = sg[bb][24 + jj] + b1[3 * Hh + j];
        int hi = bb * Hh + j;
        float co = g_c1[hi];
        float cn = sigf(fv) * co + sigf(iv) * tanhf(gv);
        float hn = sigf(ov) * tanhf(cn);
        g_c1[hi] = cn;
        g_h1[pp ^ 1][hi] = hn;
        g_h1all[(size_t)(t * Bz + bb) * Hh + j] = hn;
    }
}

// ---------------- K4: logits = h1_all @ w_out + b_out -> d_out[1..] -----------
// M=8128 (m = b*127+t, output-major), N=10000, K=1024.
__global__ __launch_bounds__(256) void k_logits(const float* __restrict__ wout,
                                                const float* __restrict__ bout,
                                                float* __restrict__ out) {
    __shared__ float As[8][128];
    __shared__ float Bs[8][128];
    __shared__ int aoff[128];

    int tid = threadIdx.x;
    int n0 = blockIdx.x * 128;
    int m0 = blockIdx.y * 128;

    if (tid < 128) {
        int m = m0 + tid;
        int mc = (m < MROWS) ? m : (MROWS - 1);
        int b = mc / 127, t = mc - b * 127;
        aoff[tid] = t * Bz + b;   // row index into g_h1all (stored (t,b,H))
    }
    __syncthreads();

    int tx = tid & 15, ty = tid >> 4;
    ull acc[8][4];
#pragma unroll
    for (int i = 0; i < 8; i++)
#pragma unroll
        for (int j = 0; j < 4; j++) acc[i][j] = 0ULL;

    for (int k0 = 0; k0 < Hh; k0 += 8) {
#pragma unroll
        for (int p = 0; p < 4; p++) {
            int idx = tid + p * 256;
            int r = idx & 127, kk = idx >> 7;
            As[kk][r] = g_h1all[(size_t)aoff[r] * Hh + k0 + kk];
            int n = n0 + r;
            Bs[kk][r] = (n < Vv) ? wout[(size_t)(k0 + kk) * Vv + n] : 0.f;
        }
        __syncthreads();
#pragma unroll
        for (int kk = 0; kk < 8; kk++) {
            ull bf[4];
#pragma unroll
            for (int j = 0; j < 4; j++) bf[j] = *(const ull*)&Bs[kk][32 * j + 2 * tx];
#pragma unroll
            for (int i = 0; i < 8; i++) {
                float a = As[kk][ty + 16 * i];
                ull a2 = pk2(a, a);
#pragma unroll
                for (int j = 0; j < 4; j++) acc[i][j] = fma2(a2, bf[j], acc[i][j]);
            }
        }
        __syncthreads();
    }

#pragma unroll
    for (int i = 0; i < 8; i++) {
        int m = m0 + ty + 16 * i;
        if (m >= MROWS) continue;
        float* orow = out + 1 + (size_t)m * Vv;
#pragma unroll
        for (int j = 0; j < 4; j++) {
            int c = 32 * j + 2 * tx;
            int n = n0 + c;              // n even, Vv even -> n<Vv implies n+1<Vv
            if (n < Vv) {
                float2 v = upk(acc[i][j]);
                orow[n]     = v.x + bout[n];
                orow[n + 1] = v.y + bout[n + 1];
            }
        }
    }
}

// ---------------- K5: per-row log-softmax at gt; masked by PAD ----------------
__global__ __launch_bounds__(256) void k_rowloss(const float* __restrict__ out,
                                                 const int* __restrict__ sent) {
    __shared__ float red[256];
    int m = blockIdx.x;
    const float* row = out + 1 + (size_t)m * Vv;
    int tid = threadIdx.x;

    float mx = -3.4e38f;
    for (int v = tid; v < Vv; v += 256) mx = fmaxf(mx, row[v]);
    red[tid] = mx; __syncthreads();
    for (int s = 128; s > 0; s >>= 1) {
        if (tid < s) red[tid] = fmaxf(red[tid], red[tid + s]);
        __syncthreads();
    }
    mx = red[0]; __syncthreads();

    float sm = 0.f;
    for (int v = tid; v < Vv; v += 256) sm += expf(row[v] - mx);
    red[tid] = sm; __syncthreads();
    for (int s = 128; s > 0; s >>= 1) {
        if (tid < s) red[tid] += red[tid + s];
        __syncthreads();
    }

    if (tid == 0) {
        int b = m / 127, t = m - b * 127;
        int gt = sent[b * Tt + t + 1];
        float lp = 0.f;
        if (gt != 0) lp = row[gt] - mx - logf(red[0]);
        g_rowloss[m] = lp;
    }
}

// ---------------- K6: deterministic loss reduction ----------------
__global__ void k_loss(const int* __restrict__ length, float* __restrict__ out) {
    __shared__ float sb[64];
    int b = threadIdx.x;   // 64 threads
    float a = 0.f;
    for (int t = 0; t < TM1; t++) a += g_rowloss[b * TM1 + t];
    sb[b] = -a / (float)length[b];
    __syncthreads();
    if (b == 0) {
        float s = 0.f;
        for (int i = 0; i < 64; i++) s += sb[i];
        out[0] = s;
    }
}

// ---------------- host ----------------
extern "C" void kernel_launch(void* const* d_in, const int* in_sizes, int n_in,
                              void* d_out, int out_size) {
    const int*   sent    = (const int*)d_in[0];
    const int*   length  = (const int*)d_in[1];
    const float* wordvec = (const float*)d_in[2];
    const float* wih0    = (const float*)d_in[3];
    const float* whh0    = (const float*)d_in[4];
    const float* b0      = (const float*)d_in[5];
    const float* wih1    = (const float*)d_in[6];
    const float* whh1    = (const float*)d_in[7];
    const float* b1      = (const float*)d_in[8];
    const float* wout    = (const float*)d_in[9];
    const float* bout    = (const float*)d_in[10];
    float* out = (float*)d_out;

    k_init<<<256, 256>>>();
    k_xw<<<dim3(G4 / 128, 64), 256>>>(sent, wordvec, wih0, b0);
    for (int t = 0; t < TM1; t++) {
        int pp = t & 1;
        k_l0<<<128, 128>>>(t, pp, whh0);
        k_l1<<<128, 128>>>(t, pp, wih1, whh1, b1);
    }
    k_logits<<<dim3((Vv + 127) / 128, 64), 256>>>(wout, bout, out);
    k_rowloss<<<MROWS, 256>>>(out, sent);
    k_loss<<<1, 64>>>(length, out);
}

// round 4
// speedup vs baseline: 1.5389x; 1.5389x over previous
#include <cuda_runtime.h>
#include <math.h>

#define Bz   64
#define Tt   128
#define TM1  127
#define Vv   10000
#define Ee   300
#define Hh   1024
#define G4   4096
#define MROWS (TM1*Bz)   // 8128
#define GRID_REC 128

typedef unsigned long long ull;

// ---------------- scratch (device globals; no allocs allowed) ----------------
__device__ float g_xw[(size_t)MROWS * G4];     // precomputed x@w_ih0 + b0, layout (t,b,4H)
__device__ float g_h1all[(size_t)MROWS * Hh];  // all h1 states, layout (t,b,H)
__device__ float g_h0[2][Bz * Hh];             // ping-pong layer0 h state
__device__ float g_h1[2][Bz * Hh];             // ping-pong layer1 h state
__device__ float g_c0[Bz * Hh];
__device__ float g_c1[Bz * Hh];
__device__ float g_rowloss[MROWS];
__device__ unsigned g_barcnt;

// ---------------- f32x2 packed-FMA helpers (sm_100+) ----------------
__device__ __forceinline__ ull pk2(float x, float y) {
    ull r; asm("mov.b64 %0, {%1,%2};" : "=l"(r) : "f"(x), "f"(y)); return r;
}
__device__ __forceinline__ ull fma2(ull a, ull b, ull c) {
    ull d; asm("fma.rn.f32x2 %0, %1, %2, %3;" : "=l"(d) : "l"(a), "l"(b), "l"(c)); return d;
}
__device__ __forceinline__ float2 upk(ull v) {
    float2 f; asm("mov.b64 {%0,%1}, %2;" : "=f"(f.x), "=f"(f.y) : "l"(v)); return f;
}
__device__ __forceinline__ float sigf(float x) { return 1.0f / (1.0f + expf(-x)); }

// grid-wide epoch barrier (all GRID_REC blocks co-resident: 128 <= #SMs)
__device__ __forceinline__ void gbar(unsigned target) {
    __syncthreads();
    if (threadIdx.x == 0) {
        __threadfence();                       // release: make my writes visible at L2
        atomicAdd(&g_barcnt, 1u);
        unsigned v;
        do {
            asm volatile("ld.acquire.gpu.u32 %0, [%1];" : "=r"(v) : "l"(&g_barcnt));
        } while (v < target);
    }
    __syncthreads();
}

// ---------------- init states ----------------
__global__ void k_init() {
    int i = blockIdx.x * blockDim.x + threadIdx.x;
    if (i < Bz * Hh) {
        g_h0[0][i] = 0.f; g_h1[0][i] = 0.f;
        g_c0[i] = 0.f;    g_c1[i] = 0.f;
    }
    if (i == 0) g_barcnt = 0u;
}

// ---------------- K2: xW = gather(emb) @ w_ih0 + b0 (unchanged) ----------------
__global__ __launch_bounds__(256) void k_xw(const int* __restrict__ sent,
                                            const float* __restrict__ wordvec,
                                            const float* __restrict__ wih0,
                                            const float* __restrict__ b0) {
    __shared__ float As[8][128];
    __shared__ float Bs[8][128];
    __shared__ int stok[128];

    int tid = threadIdx.x;
    int n0 = blockIdx.x * 128;
    int m0 = blockIdx.y * 128;

    if (tid < 128) {
        int m = m0 + tid;
        int mc = (m < MROWS) ? m : (MROWS - 1);
        int t = mc >> 6, b = mc & 63;
        stok[tid] = sent[b * Tt + t];
    }
    __syncthreads();

    int tx = tid & 15, ty = tid >> 4;
    ull acc[8][4];
#pragma unroll
    for (int i = 0; i < 8; i++)
#pragma unroll
        for (int j = 0; j < 4; j++) acc[i][j] = 0ULL;

    for (int k0 = 0; k0 < Ee; k0 += 8) {
#pragma unroll
        for (int p = 0; p < 4; p++) {
            int idx = tid + p * 256;
            int r = idx & 127, kk = idx >> 7;
            int k = k0 + kk;
            As[kk][r] = (k < Ee) ? wordvec[(size_t)stok[r] * Ee + k] : 0.f;
            Bs[kk][r] = (k < Ee) ? wih0[(size_t)k * G4 + n0 + r] : 0.f;
        }
        __syncthreads();
#pragma unroll
        for (int kk = 0; kk < 8; kk++) {
            ull bf[4];
#pragma unroll
            for (int j = 0; j < 4; j++) bf[j] = *(const ull*)&Bs[kk][32 * j + 2 * tx];
#pragma unroll
            for (int i = 0; i < 8; i++) {
                float a = As[kk][ty + 16 * i];
                ull a2 = pk2(a, a);
#pragma unroll
                for (int j = 0; j < 4; j++) acc[i][j] = fma2(a2, bf[j], acc[i][j]);
            }
        }
        __syncthreads();
    }

#pragma unroll
    for (int i = 0; i < 8; i++) {
        int m = m0 + ty + 16 * i;
        if (m >= MROWS) continue;
        float* orow = g_xw + (size_t)m * G4 + n0;
#pragma unroll
        for (int j = 0; j < 4; j++) {
            float2 v = upk(acc[i][j]);
            int c = 32 * j + 2 * tx;
            orow[c]     = v.x + b0[n0 + c];
            orow[c + 1] = v.y + b0[n0 + c + 1];
        }
    }
}

// ---------------- K3: persistent fused recurrence ----------------
// 128 blocks x 256 threads; block owns 8 hidden units j0=bid*8 (32 gate cols).
// Rowpair-packed f32x2 GEMM: tile 64(batch) x 32(gatecols), chunks of 32 k,
// double-buffered smem w/ register prefetch; 2 grid barriers per step.
__global__ __launch_bounds__(256) void k_rec(const float* __restrict__ whh0,
                                             const float* __restrict__ wih1,
                                             const float* __restrict__ whh1,
                                             const float* __restrict__ b1) {
    __shared__ __align__(16) float sh_h[2][32][68];
    __shared__ __align__(16) ull   sh_w[2][32][32];
    __shared__ __align__(16) float sg[64][33];

    const int tid = threadIdx.x;
    const int j0  = blockIdx.x * 8;
    const int tx  = tid & 15, ty = tid >> 4;        // compute map
    const int fb  = tid >> 2, fq = tid & 3;         // h fill: batch, k-quarter
    const int fkk = tid >> 3;                       // w fill: kk in chunk
    const int fg  = (tid & 7) >> 1, fh = tid & 1;   // w fill: gate, half
    const int wcol = fg * Hh + j0 + fh * 4;         // gmem col base
    const int wsc  = fg * 8 + fh * 4;               // smem col base

    unsigned tgt = 0;

    for (int t = 0; t < TM1; t++) {
        const int pp = t & 1;

        // ================= phase A: layer0 =================
        {
            const float* hsrc = g_h0[pp];
            ull a00 = 0, a10 = 0, a01 = 0, a11 = 0;
            float4 ph0, ph1, pw;

            auto sts = [&](int b2) {
                sh_h[b2][fq * 8 + 0][fb] = ph0.x; sh_h[b2][fq * 8 + 1][fb] = ph0.y;
                sh_h[b2][fq * 8 + 2][fb] = ph0.z; sh_h[b2][fq * 8 + 3][fb] = ph0.w;
                sh_h[b2][fq * 8 + 4][fb] = ph1.x; sh_h[b2][fq * 8 + 5][fb] = ph1.y;
                sh_h[b2][fq * 8 + 6][fb] = ph1.z; sh_h[b2][fq * 8 + 7][fb] = ph1.w;
                ull* wsp = &sh_w[b2][fkk][wsc];
                wsp[0] = pk2(pw.x, pw.x); wsp[1] = pk2(pw.y, pw.y);
                wsp[2] = pk2(pw.z, pw.z); wsp[3] = pk2(pw.w, pw.w);
            };
            auto comp = [&](int b2) {
#pragma unroll
                for (int kk = 0; kk < 32; kk++) {
                    ulonglong2 hA = *(const ulonglong2*)&sh_h[b2][kk][4 * ty];
                    ulonglong2 wB = *(const ulonglong2*)&sh_w[b2][kk][2 * tx];
                    a00 = fma2(hA.x, wB.x, a00);
                    a10 = fma2(hA.y, wB.x, a10);
                    a01 = fma2(hA.x, wB.y, a01);
                    a11 = fma2(hA.y, wB.y, a11);
                }
            };

            ph0 = __ldcg((const float4*)(hsrc + fb * Hh + fq * 8));
            ph1 = __ldcg((const float4*)(hsrc + fb * Hh + fq * 8 + 4));
            pw  = __ldg ((const float4*)(whh0 + (size_t)fkk * G4 + wcol));
            int buf = 0;
            sts(buf);
            __syncthreads();
            const int NC = Hh / 32;
            for (int c = 0; c < NC; c++) {
                if (c + 1 < NC) {
                    int kb = (c + 1) * 32;
                    ph0 = __ldcg((const float4*)(hsrc + fb * Hh + kb + fq * 8));
                    ph1 = __ldcg((const float4*)(hsrc + fb * Hh + kb + fq * 8 + 4));
                    pw  = __ldg ((const float4*)(whh0 + (size_t)(kb + fkk) * G4 + wcol));
                }
                comp(buf);
                if (c + 1 < NC) sts(buf ^ 1);
                __syncthreads();
                buf ^= 1;
            }
            // stage to sg
            {
                float2 v;
                v = upk(a00); sg[4 * ty + 0][2 * tx]     = v.x; sg[4 * ty + 1][2 * tx]     = v.y;
                v = upk(a10); sg[4 * ty + 2][2 * tx]     = v.x; sg[4 * ty + 3][2 * tx]     = v.y;
                v = upk(a01); sg[4 * ty + 0][2 * tx + 1] = v.x; sg[4 * ty + 1][2 * tx + 1] = v.y;
                v = upk(a11); sg[4 * ty + 2][2 * tx + 1] = v.x; sg[4 * ty + 3][2 * tx + 1] = v.y;
            }
            __syncthreads();
            // cell update (block owns units j0..j0+7, all 64 batches)
            const float* xwbase = g_xw + (size_t)t * Bz * G4;
#pragma unroll
            for (int e = 0; e < 2; e++) {
                int idx = tid + e * 256;
                int bb = idx & 63, jj = idx >> 6;
                const float* xwr = xwbase + (size_t)bb * G4 + j0 + jj;
                float iv = sg[bb][jj]      + xwr[0];
                float fv = sg[bb][8 + jj]  + xwr[Hh];
                float gv = sg[bb][16 + jj] + xwr[2 * Hh];
                float ov = sg[bb][24 + jj] + xwr[3 * Hh];
                int hi = bb * Hh + j0 + jj;
                float co = g_c0[hi];
                float cn = sigf(fv) * co + sigf(iv) * tanhf(gv);
                float hn = sigf(ov) * tanhf(cn);
                g_c0[hi] = cn;
                g_h0[pp ^ 1][hi] = hn;
            }
        }
        tgt += GRID_REC; gbar(tgt);

        // ================= phase B: layer1 (K=2048) =================
        {
            const float* h0n = g_h0[pp ^ 1];
            const float* h1o = g_h1[pp];
            ull a00 = 0, a10 = 0, a01 = 0, a11 = 0;
            float4 ph0, ph1, pw;

            auto sts = [&](int b2) {
                sh_h[b2][fq * 8 + 0][fb] = ph0.x; sh_h[b2][fq * 8 + 1][fb] = ph0.y;
                sh_h[b2][fq * 8 + 2][fb] = ph0.z; sh_h[b2][fq * 8 + 3][fb] = ph0.w;
                sh_h[b2][fq * 8 + 4][fb] = ph1.x; sh_h[b2][fq * 8 + 5][fb] = ph1.y;
                sh_h[b2][fq * 8 + 6][fb] = ph1.z; sh_h[b2][fq * 8 + 7][fb] = ph1.w;
                ull* wsp = &sh_w[b2][fkk][wsc];
                wsp[0] = pk2(pw.x, pw.x); wsp[1] = pk2(pw.y, pw.y);
                wsp[2] = pk2(pw.z, pw.z); wsp[3] = pk2(pw.w, pw.w);
            };
            auto comp = [&](int b2) {
#pragma unroll
                for (int kk = 0; kk < 32; kk++) {
                    ulonglong2 hA = *(const ulonglong2*)&sh_h[b2][kk][4 * ty];
                    ulonglong2 wB = *(const ulonglong2*)&sh_w[b2][kk][2 * tx];
                    a00 = fma2(hA.x, wB.x, a00);
                    a10 = fma2(hA.y, wB.x, a10);
                    a01 = fma2(hA.x, wB.y, a01);
                    a11 = fma2(hA.y, wB.y, a11);
                }
            };

            ph0 = __ldcg((const float4*)(h0n + fb * Hh + fq * 8));
            ph1 = __ldcg((const float4*)(h0n + fb * Hh + fq * 8 + 4));
            pw  = __ldg ((const float4*)(wih1 + (size_t)fkk * G4 + wcol));
            int buf = 0;
            sts(buf);
            __syncthreads();
            const int NC = 2 * Hh / 32;
            for (int c = 0; c < NC; c++) {
                if (c + 1 < NC) {
                    int kn = (c + 1) * 32;
                    const float* hs = (kn < Hh) ? h0n : h1o;
                    const float* wg = (kn < Hh) ? wih1 : whh1;
                    int kb = kn & (Hh - 1);
                    ph0 = __ldcg((const float4*)(hs + fb * Hh + kb + fq * 8));
                    ph1 = __ldcg((const float4*)(hs + fb * Hh + kb + fq * 8 + 4));
                    pw  = __ldg ((const float4*)(wg + (size_t)(kb + fkk) * G4 + wcol));
                }
                comp(buf);
                if (c + 1 < NC) sts(buf ^ 1);
                __syncthreads();
                buf ^= 1;
            }
            {
                float2 v;
                v = upk(a00); sg[4 * ty + 0][2 * tx]     = v.x; sg[4 * ty + 1][2 * tx]     = v.y;
                v = upk(a10); sg[4 * ty + 2][2 * tx]     = v.x; sg[4 * ty + 3][2 * tx]     = v.y;
                v = upk(a01); sg[4 * ty + 0][2 * tx + 1] = v.x; sg[4 * ty + 1][2 * tx + 1] = v.y;
                v = upk(a11); sg[4 * ty + 2][2 * tx + 1] = v.x; sg[4 * ty + 3][2 * tx + 1] = v.y;
            }
            __syncthreads();
#pragma unroll
            for (int e = 0; e < 2; e++) {
                int idx = tid + e * 256;
                int bb = idx & 63, jj = idx >> 6;
                int col = j0 + jj;
                float iv = sg[bb][jj]      + b1[col];
                float fv = sg[bb][8 + jj]  + b1[Hh + col];
                float gv = sg[bb][16 + jj] + b1[2 * Hh + col];
                float ov = sg[bb][24 + jj] + b1[3 * Hh + col];
                int hi = bb * Hh + col;
                float co = g_c1[hi];
                float cn = sigf(fv) * co + sigf(iv) * tanhf(gv);
                float hn = sigf(ov) * tanhf(cn);
                g_c1[hi] = cn;
                g_h1[pp ^ 1][hi] = hn;
                g_h1all[((size_t)t * Bz + bb) * Hh + col] = hn;
            }
        }
        tgt += GRID_REC; gbar(tgt);
    }
}

// ---------------- K4: logits = h1_all @ w_out + b_out (rowpair f32x2) ----------
// tile 128(m) x 128(n), 256 thr, thread: 16 rows (8 rowpairs) x 4 cols = 32 ull acc
__global__ __launch_bounds__(256, 2) void k_logits(const float* __restrict__ wout,
                                                   const float* __restrict__ bout,
                                                   float* __restrict__ out) {
    __shared__ __align__(16) float As[8][132];
    __shared__ __align__(16) ull   Bd[8][128];
    __shared__ int aoff[128];

    int tid = threadIdx.x;
    int n0 = blockIdx.x * 128;
    int m0 = blockIdx.y * 128;

    if (tid < 128) {
        int m = m0 + tid;
        int mc = (m < MROWS) ? m : (MROWS - 1);
        int b = mc / 127, t = mc - b * 127;
        aoff[tid] = t * Bz + b;
    }
    __syncthreads();

    int tx = tid & 31, wy = tid >> 5;
    int ar = tid >> 1, akq = tid & 1;
    int bkk = tid >> 5, bc = (tid & 31) * 4;
    bool bok = (n0 + bc + 3 < Vv);

    ull acc[8][4];
#pragma unroll
    for (int p = 0; p < 8; p++)
#pragma unroll
        for (int j = 0; j < 4; j++) acc[p][j] = 0ULL;

    for (int k0 = 0; k0 < Hh; k0 += 8) {
        float4 av = __ldg((const float4*)(g_h1all + (size_t)aoff[ar] * Hh + k0 + akq * 4));
        float4 bv = make_float4(0.f, 0.f, 0.f, 0.f);
        if (bok) {
            bv = __ldg((const float4*)(wout + (size_t)(k0 + bkk) * Vv + n0 + bc));
        } else {
            const float* wr = wout + (size_t)(k0 + bkk) * Vv;
            if (n0 + bc + 0 < Vv) bv.x = wr[n0 + bc + 0];
            if (n0 + bc + 1 < Vv) bv.y = wr[n0 + bc + 1];
            if (n0 + bc + 2 < Vv) bv.z = wr[n0 + bc + 2];
            if (n0 + bc + 3 < Vv) bv.w = wr[n0 + bc + 3];
        }
        __syncthreads();
        As[akq * 4 + 0][ar] = av.x; As[akq * 4 + 1][ar] = av.y;
        As[akq * 4 + 2][ar] = av.z; As[akq * 4 + 3][ar] = av.w;
        Bd[bkk][bc + 0] = pk2(bv.x, bv.x); Bd[bkk][bc + 1] = pk2(bv.y, bv.y);
        Bd[bkk][bc + 2] = pk2(bv.z, bv.z); Bd[bkk][bc + 3] = pk2(bv.w, bv.w);
        __syncthreads();
#pragma unroll
        for (int kk = 0; kk < 8; kk++) {
            ulonglong2 A0 = *(const ulonglong2*)&As[kk][wy * 16 + 0];
            ulonglong2 A1 = *(const ulonglong2*)&As[kk][wy * 16 + 4];
            ulonglong2 A2 = *(const ulonglong2*)&As[kk][wy * 16 + 8];
            ulonglong2 A3 = *(const ulonglong2*)&As[kk][wy * 16 + 12];
            ull hr[8] = {A0.x, A0.y, A1.x, A1.y, A2.x, A2.y, A3.x, A3.y};
#pragma unroll
            for (int j = 0; j < 4; j++) {
                ull w = Bd[kk][tx + 32 * j];
#pragma unroll
                for (int p = 0; p < 8; p++) acc[p][j] = fma2(hr[p], w, acc[p][j]);
            }
        }
    }

#pragma unroll
    for (int p = 0; p < 8; p++) {
        int m = m0 + wy * 16 + 2 * p;
#pragma unroll
        for (int j = 0; j < 4; j++) {
            int n = n0 + tx + 32 * j;
            if (n < Vv) {
                float2 v = upk(acc[p][j]);
                float bo = bout[n];
                if (m < MROWS)     out[1 + (size_t)m * Vv + n]       = v.x + bo;
                if (m + 1 < MROWS) out[1 + (size_t)(m + 1) * Vv + n] = v.y + bo;
            }
        }
    }
}

// ---------------- K5: per-row log-softmax at gt; masked by PAD ----------------
__global__ __launch_bounds__(256) void k_rowloss(const float* __restrict__ out,
                                                 const int* __restrict__ sent) {
    __shared__ float red[256];
    int m = blockIdx.x;
    const float* row = out + 1 + (size_t)m * Vv;
    int tid = threadIdx.x;

    float mx = -3.4e38f;
    for (int v = tid; v < Vv; v += 256) mx = fmaxf(mx, row[v]);
    red[tid] = mx; __syncthreads();
    for (int s = 128; s > 0; s >>= 1) {
        if (tid < s) red[tid] = fmaxf(red[tid], red[tid + s]);
        __syncthreads();
    }
    mx = red[0]; __syncthreads();

    float sm = 0.f;
    for (int v = tid; v < Vv; v += 256) sm += expf(row[v] - mx);
    red[tid] = sm; __syncthreads();
    for (int s = 128; s > 0; s >>= 1) {
        if (tid < s) red[tid] += red[tid + s];
        __syncthreads();
    }

    if (tid == 0) {
        int b = m / 127, t = m - b * 127;
        int gt = sent[b * Tt + t + 1];
        float lp = 0.f;
        if (gt != 0) lp = row[gt] - mx - logf(red[0]);
        g_rowloss[m] = lp;
    }
}

// ---------------- K6: deterministic loss reduction ----------------
__global__ void k_loss(const int* __restrict__ length, float* __restrict__ out) {
    __shared__ float sb[64];
    int b = threadIdx.x;
    float a = 0.f;
    for (int t = 0; t < TM1; t++) a += g_rowloss[b * TM1 + t];
    sb[b] = -a / (float)length[b];
    __syncthreads();
    if (b == 0) {
        float s = 0.f;
        for (int i = 0; i < 64; i++) s += sb[i];
        out[0] = s;
    }
}

// ---------------- host ----------------
extern "C" void kernel_launch(void* const* d_in, const int* in_sizes, int n_in,
                              void* d_out, int out_size) {
    const int*   sent    = (const int*)d_in[0];
    const int*   length  = (const int*)d_in[1];
    const float* wordvec = (const float*)d_in[2];
    const float* wih0    = (const float*)d_in[3];
    const float* whh0    = (const float*)d_in[4];
    const float* b0      = (const float*)d_in[5];
    const float* wih1    = (const float*)d_in[6];
    const float* whh1    = (const float*)d_in[7];
    const float* b1      = (const float*)d_in[8];
    const float* wout    = (const float*)d_in[9];
    const float* bout    = (const float*)d_in[10];
    float* out = (float*)d_out;

    k_init<<<256, 256>>>();
    k_xw<<<dim3(G4 / 128, 64), 256>>>(sent, wordvec, wih0, b0);
    k_rec<<<GRID_REC, 256>>>(whh0, wih1, whh1, b1);
    k_logits<<<dim3((Vv + 127) / 128, (MROWS + 127) / 128), 256>>>(wout, bout, out);
    k_rowloss<<<MROWS, 256>>>(out, sent);
    k_loss<<<1, 64>>>(length, out);
}